// round 2
// baseline (speedup 1.0000x reference)
#include <cuda_runtime.h>
#include <stdint.h>

#define F_DIM   1024
#define C_DIM   64
#define NROWS   65536
#define TPB     128
#define NBINS   256

// Scratch (allocation-free rule: __device__ globals)
__device__ uint32_t       d_seg_packed[F_DIM / 4]; // fine -> coarse id, 4 per word
__device__ unsigned short d_perm[F_DIM];           // fine indices sorted by coarse id
__device__ int            d_offs[C_DIM + 1];       // CSR offsets per coarse group
__device__ int            d_lbl_is64;              // 1 if labels buffer is int64
__device__ double         d_partial[NBINS];        // per-bin loss accumulators

// ---------------------------------------------------------------------------
// Setup: seg ids from one-hot mask, CSR permutation, label-dtype detection,
// zero accumulators. 1 block, 1024 threads.
// ---------------------------------------------------------------------------
__global__ void setup_kernel(const float* __restrict__ mask,
                             const int*   __restrict__ labels32) {
    __shared__ int cnt[C_DIM];
    __shared__ int offs[C_DIM + 1];
    __shared__ int cursor[C_DIM];
    __shared__ int odd_or;

    int t = threadIdx.x;           // 0..1023 == fine index
    if (t < C_DIM) { cnt[t] = 0; cursor[t] = 0; }
    if (t < NBINS) d_partial[t] = 0.0;
    if (t == 0) odd_or = 0;
    __syncthreads();

    // --- label dtype detection: safe to read NROWS int32 words either way.
    // int64 labels (values<64, LE) -> all odd words are 0. int32 -> random.
    int my_or = 0;
    for (int i = 2 * t + 1; i < NROWS; i += 2048)
        my_or |= labels32[i];
    if (my_or) atomicOr(&odd_or, 1);

    // --- one-hot row: exactly one 1.0
    const float* row = mask + (size_t)t * C_DIM;
    int c = 0;
    #pragma unroll 8
    for (int j = 0; j < C_DIM; j++) if (row[j] > 0.5f) c = j;
    ((unsigned char*)d_seg_packed)[t] = (unsigned char)c;
    atomicAdd(&cnt[c], 1);
    __syncthreads();

    if (t == 0) {
        int acc = 0;
        for (int i = 0; i < C_DIM; i++) { offs[i] = acc; acc += cnt[i]; }
        offs[C_DIM] = acc;
        d_lbl_is64 = (odd_or == 0) ? 1 : 0;
    }
    __syncthreads();
    if (t <= C_DIM) d_offs[t] = offs[t];

    int pos = offs[c] + atomicAdd(&cursor[c], 1);   // order within group irrelevant (max)
    d_perm[pos] = (unsigned short)t;
}

// ---------------------------------------------------------------------------
// Main: one block per row. Coalesced float4 row load (regs + smem mirror),
// CSR gather for group maxes (no atomics), single exp per element from regs.
// ---------------------------------------------------------------------------
__global__ void __launch_bounds__(TPB) mixloss_kernel(
    const float* __restrict__ logits,
    const void*  __restrict__ labels)
{
    __shared__ float s_row[F_DIM];
    __shared__ float s_gmax[C_DIM];
    __shared__ float s_sums[8];       // [0..3] sum_all per warp, [4..7] sum_label
    __shared__ float s_M;
    __shared__ float s_Sc;

    const int r = blockIdx.x;
    const int t = threadIdx.x;

    // --- Phase 1: coalesced load, keep in registers AND mirror to smem ---
    const float4* rowp = (const float4*)(logits + (size_t)r * F_DIM);
    float4 a = rowp[t];
    float4 b = rowp[t + TPB];
    float4* srow4 = (float4*)s_row;
    srow4[t]       = a;
    srow4[t + TPB] = b;
    __syncthreads();

    // --- Phase 2: group maxes via CSR gather (threads 0..63) ---
    if (t < C_DIM) {
        int beg = d_offs[t], end = d_offs[t + 1];
        float gm = -3.402823466e38f;
        for (int i = beg; i < end; i++)
            gm = fmaxf(gm, s_row[d_perm[i]]);
        s_gmax[t] = gm;
    }
    __syncthreads();

    // --- Phase 3: warp 0 computes M (global max) and coarse exp-sum Sc ---
    if (t < 32) {
        float g0 = s_gmax[t], g1 = s_gmax[t + 32];
        float m = fmaxf(g0, g1);
        #pragma unroll
        for (int o = 16; o > 0; o >>= 1)
            m = fmaxf(m, __shfl_xor_sync(0xffffffffu, m, o));
        // all lanes now hold M
        float sc = __expf(g0 - m) + __expf(g1 - m);
        #pragma unroll
        for (int o = 16; o > 0; o >>= 1)
            sc += __shfl_xor_sync(0xffffffffu, sc, o);
        if (t == 0) { s_M = m; s_Sc = sc; }
    }
    __syncthreads();

    const float M = s_M;
    int lbl;
    if (d_lbl_is64) lbl = (int)((const long long*)labels)[r];
    else            lbl = ((const int*)labels)[r];
    lbl &= (C_DIM - 1);   // insurance against smem OOB

    // --- Phase 4: exp sums from registers (one exp per element) ---
    uint32_t seg0 = d_seg_packed[t];
    uint32_t seg1 = d_seg_packed[t + TPB];
    float v[8] = {a.x, a.y, a.z, a.w, b.x, b.y, b.z, b.w};
    float sa = 0.f, sl = 0.f;
    #pragma unroll
    for (int j = 0; j < 8; j++) {
        float e = __expf(v[j] - M);
        sa += e;
        uint32_t sg = ((j < 4 ? seg0 : seg1) >> ((j & 3) * 8)) & 0xffu;
        if ((int)sg == lbl) sl += e;
    }
    #pragma unroll
    for (int o = 16; o > 0; o >>= 1) {
        sa += __shfl_xor_sync(0xffffffffu, sa, o);
        sl += __shfl_xor_sync(0xffffffffu, sl, o);
    }
    int w = t >> 5;
    if ((t & 31) == 0) { s_sums[w] = sa; s_sums[4 + w] = sl; }
    __syncthreads();

    // --- Phase 5: per-row loss -> binned fp64 accumulator ---
    if (t == 0) {
        float SA = s_sums[0] + s_sums[1] + s_sums[2] + s_sums[3];
        float SL = s_sums[4] + s_sums[5] + s_sums[6] + s_sums[7];
        float ce  = M + __logf(s_Sc) - s_gmax[lbl];   // -log_softmax(coarse_max)[lbl]
        float nll = __logf(SA) - __logf(SL);          // -log(p_coarse[lbl])
        atomicAdd(&d_partial[r & (NBINS - 1)], (double)(0.5f * (ce + nll)));
    }
}

// ---------------------------------------------------------------------------
// Final: reduce 256 fp64 bins -> scalar fp32 mean.
// ---------------------------------------------------------------------------
__global__ void final_kernel(float* __restrict__ out) {
    __shared__ double s[NBINS];
    int t = threadIdx.x;
    s[t] = d_partial[t];
    __syncthreads();
    for (int o = NBINS / 2; o > 0; o >>= 1) {
        if (t < o) s[t] += s[t + o];
        __syncthreads();
    }
    if (t == 0) out[0] = (float)(s[0] / (double)NROWS);
}

extern "C" void kernel_launch(void* const* d_in, const int* in_sizes, int n_in,
                              void* d_out, int out_size) {
    const float* logits = (const float*)d_in[0];
    const void*  labels = d_in[1];
    const float* mask   = (const float*)d_in[2];

    setup_kernel<<<1, 1024>>>(mask, (const int*)labels);
    mixloss_kernel<<<NROWS, TPB>>>(logits, labels);
    final_kernel<<<1, NBINS>>>((float*)d_out);
}

// round 3
// speedup vs baseline: 1.2747x; 1.2747x over previous
#include <cuda_runtime.h>
#include <stdint.h>
#include <float.h>

#define F_DIM   1024
#define C_DIM   64
#define NROWS   65536
#define TPB     128
#define NBINS   256
#define PROW_MAX (F_DIM + C_DIM * 8)   // padded row upper bound (1536)

// Scratch (allocation-free rule: __device__ globals)
__device__ uint32_t       d_seg_packed[F_DIM / 4]; // fine -> coarse id, 4/word
__device__ unsigned short d_pos[F_DIM];            // fine -> padded-CSR slot
__device__ int            d_poffs[C_DIM + 1];      // padded CSR offsets (mult. of 8)
__device__ int            d_gcnt[C_DIM];           // real count per group
__device__ int            d_oddor_part[8];         // label dtype detection parts
__device__ int            d_lbl_is64;
__device__ double         d_partial[NBINS];

// ---------------------------------------------------------------------------
// S1: 8 blocks x 128. Parallel seg-id compute, label-dtype OR parts,
// zero partial bins. No cross-block accumulators (plain stores only).
// ---------------------------------------------------------------------------
__global__ void setup1_kernel(const float* __restrict__ mask,
                              const int*   __restrict__ labels32) {
    __shared__ int s_or;
    int b = blockIdx.x, t = threadIdx.x;
    int f = b * TPB + t;                 // 0..1023 fine index
    if (t == 0) s_or = 0;
    if (t < 32) d_partial[b * 32 + t] = 0.0;
    __syncthreads();

    // one-hot row -> coarse id
    const float* row = mask + (size_t)f * C_DIM;
    int c = 0;
    #pragma unroll 8
    for (int j = 0; j < C_DIM; j++) if (row[j] > 0.5f) c = j;
    ((unsigned char*)d_seg_packed)[f] = (unsigned char)c;

    // label dtype: int64 labels (<64, LE) have all odd int32 words == 0
    int my_or = 0;
    for (int i = 2 * f + 1; i < NROWS; i += 2 * F_DIM)
        my_or |= labels32[i];
    if (my_or) atomicOr(&s_or, 1);
    __syncthreads();
    if (t == 0) d_oddor_part[b] = s_or;
}

// ---------------------------------------------------------------------------
// S2: 1 block x 1024. Counts, padded-offset scan, scatter positions.
// ---------------------------------------------------------------------------
__global__ void setup2_kernel(void) {
    __shared__ int cnt[C_DIM];
    __shared__ int offs[C_DIM + 1];
    __shared__ int cursor[C_DIM];

    int t = threadIdx.x;                 // == fine index
    if (t < C_DIM) { cnt[t] = 0; cursor[t] = 0; }
    __syncthreads();

    int c = ((const unsigned char*)d_seg_packed)[t];
    atomicAdd(&cnt[c], 1);
    __syncthreads();

    if (t == 0) {
        int acc = 0, oor = 0;
        for (int i = 0; i < 8; i++) oor |= d_oddor_part[i];
        d_lbl_is64 = (oor == 0) ? 1 : 0;
        for (int i = 0; i < C_DIM; i++) {
            offs[i] = acc;
            acc += (cnt[i] + 7) & ~7;    // pad each group to 8 floats
        }
        offs[C_DIM] = acc;
    }
    __syncthreads();
    if (t <= C_DIM) d_poffs[t] = offs[t];
    if (t <  C_DIM) d_gcnt[t]  = cnt[t];

    int pos = offs[c] + atomicAdd(&cursor[c], 1);
    d_pos[t] = (unsigned short)pos;
}

// ---------------------------------------------------------------------------
// Main: one block per row.
//  P1: coalesced float4 load -> regs, scatter to group-contiguous smem;
//      threads<64 also fill pad slots with -FLT_MAX (disjoint -> same barrier)
//  P2: group max: 2 threads/group, sequential float4 LDS
//  P3: every warp redundantly computes M (global max) + Sc (no extra barrier)
//  P4: exp sums from registers, warp shfl reduce
//  P5: thread 0 -> per-row loss -> binned fp64 atomic
// ---------------------------------------------------------------------------
__global__ void __launch_bounds__(TPB) mixloss_kernel(
    const float* __restrict__ logits,
    const void*  __restrict__ labels)
{
    __shared__ float s_prow[PROW_MAX];
    __shared__ float s_gmax[C_DIM];
    __shared__ float s_sums[8];

    const int r = blockIdx.x;
    const int t = threadIdx.x;
    const int lane = t & 31, w = t >> 5;

    // --- P1 ---
    const float4* rowp = (const float4*)(logits + (size_t)r * F_DIM);
    float4 a = rowp[t];
    float4 b = rowp[t + TPB];

    // scatter positions: 4 contiguous ushorts per quad
    ushort4 p0 = *(const ushort4*)(d_pos + 4 * t);
    ushort4 p1 = *(const ushort4*)(d_pos + 4 * (t + TPB));
    s_prow[p0.x] = a.x; s_prow[p0.y] = a.y; s_prow[p0.z] = a.z; s_prow[p0.w] = a.w;
    s_prow[p1.x] = b.x; s_prow[p1.y] = b.y; s_prow[p1.z] = b.z; s_prow[p1.w] = b.w;

    if (t < C_DIM) {
        int beg = d_poffs[t], cn = d_gcnt[t];
        int plen = (cn + 7) & ~7;
        for (int i = cn; i < plen; i++) s_prow[beg + i] = -FLT_MAX;
    }
    __syncthreads();

    // --- P2: group maxes, 2 threads per group ---
    {
        int g = t >> 1, half = t & 1;
        int beg = d_poffs[g], end = d_poffs[g + 1];
        float4 m4 = make_float4(-FLT_MAX, -FLT_MAX, -FLT_MAX, -FLT_MAX);
        for (int i = beg + half * 4; i < end; i += 8) {
            float4 v = *(const float4*)(s_prow + i);
            m4.x = fmaxf(m4.x, v.x); m4.y = fmaxf(m4.y, v.y);
            m4.z = fmaxf(m4.z, v.z); m4.w = fmaxf(m4.w, v.w);
        }
        float m = fmaxf(fmaxf(m4.x, m4.y), fmaxf(m4.z, m4.w));
        m = fmaxf(m, __shfl_xor_sync(0xffffffffu, m, 1));
        if (half == 0) s_gmax[g] = m;
    }
    __syncthreads();

    // --- P3: each warp computes M and Sc independently ---
    float g0 = s_gmax[lane], g1 = s_gmax[lane + 32];
    float M = fmaxf(g0, g1);
    #pragma unroll
    for (int o = 16; o > 0; o >>= 1)
        M = fmaxf(M, __shfl_xor_sync(0xffffffffu, M, o));
    float Sc = __expf(g0 - M) + __expf(g1 - M);
    #pragma unroll
    for (int o = 16; o > 0; o >>= 1)
        Sc += __shfl_xor_sync(0xffffffffu, Sc, o);

    int lbl;
    if (d_lbl_is64) lbl = (int)((const long long*)labels)[r];
    else            lbl = ((const int*)labels)[r];
    lbl &= (C_DIM - 1);

    // --- P4: exp sums from registers ---
    uint32_t seg0 = d_seg_packed[t];
    uint32_t seg1 = d_seg_packed[t + TPB];
    float v[8] = {a.x, a.y, a.z, a.w, b.x, b.y, b.z, b.w};
    float sa = 0.f, sl = 0.f;
    #pragma unroll
    for (int j = 0; j < 8; j++) {
        float e = __expf(v[j] - M);
        sa += e;
        uint32_t sg = ((j < 4 ? seg0 : seg1) >> ((j & 3) * 8)) & 0xffu;
        if ((int)sg == lbl) sl += e;
    }
    #pragma unroll
    for (int o = 16; o > 0; o >>= 1) {
        sa += __shfl_xor_sync(0xffffffffu, sa, o);
        sl += __shfl_xor_sync(0xffffffffu, sl, o);
    }
    if (lane == 0) { s_sums[w] = sa; s_sums[4 + w] = sl; }
    __syncthreads();

    // --- P5 ---
    if (t == 0) {
        float SA = s_sums[0] + s_sums[1] + s_sums[2] + s_sums[3];
        float SL = s_sums[4] + s_sums[5] + s_sums[6] + s_sums[7];
        float ce  = M + __logf(Sc) - s_gmax[lbl];
        float nll = __logf(SA) - __logf(SL);
        atomicAdd(&d_partial[r & (NBINS - 1)], (double)(0.5f * (ce + nll)));
    }
}

// ---------------------------------------------------------------------------
// Final: reduce 256 fp64 bins -> scalar fp32 mean.
// ---------------------------------------------------------------------------
__global__ void final_kernel(float* __restrict__ out) {
    __shared__ double s[NBINS];
    int t = threadIdx.x;
    s[t] = d_partial[t];
    __syncthreads();
    for (int o = NBINS / 2; o > 0; o >>= 1) {
        if (t < o) s[t] += s[t + o];
        __syncthreads();
    }
    if (t == 0) out[0] = (float)(s[0] / (double)NROWS);
}

extern "C" void kernel_launch(void* const* d_in, const int* in_sizes, int n_in,
                              void* d_out, int out_size) {
    const float* logits = (const float*)d_in[0];
    const void*  labels = d_in[1];
    const float* mask   = (const float*)d_in[2];

    setup1_kernel<<<8, TPB>>>(mask, (const int*)labels);
    setup2_kernel<<<1, 1024>>>();
    mixloss_kernel<<<NROWS, TPB>>>(logits, labels);
    final_kernel<<<1, NBINS>>>((float*)d_out);
}